// round 11
// baseline (speedup 1.0000x reference)
#include <cuda_runtime.h>
#include <cuda_fp16.h>

// Problem shape (fixed by the dataset)
#define BATCH 8
#define CHAN  3
#define HH    720
#define WW    1280
#define HW    (HH * WW)
#define NROWS (BATCH * HH)
#define EPSV  1e-6f
#define K_LOG2 0.49978218f     // log2(1.414)

// flow_y == 0 -> 1-D row splat: pixel x hits bins x0=floor(x-d) and x0+1.
// (c0,c1) and (c2,wsum) accumulate as two __half2 shared planes per row via
// return-free red.shared.add.noftz.f16x2 (R10: -6.4us vs atomicAdd).
// 4 REDs/pixel is the exact payload floor (8 f16 scalars / 2 per 32-bit RED).
//
// R11: two rows per block. RED lane rate (~2.4 lanes/cyc/SM) pins l1tex busy
// at ~46us; the remaining 10us is barrier/zero/tail exposure. Processing two
// rows per block halves syncthreads per row and interleaves independent RED
// bursts to close the issue-idle gap.
//
// Bank hash (bits [2:5)): slot = bin ^ ((bin>>5)&28); aligned 4-bin groups
// stay contiguous -> uint4 readback.
__device__ __forceinline__ int bhash(int bin) {
    return bin ^ ((bin >> 5) & 28);
}

__device__ __forceinline__ void red_sh_h2(unsigned addr, unsigned val) {
    asm volatile("red.shared.add.noftz.f16x2 [%0], %1;"
                 :: "r"(addr), "r"(val) : "memory");
}

__device__ __forceinline__ unsigned pack_h2(float a, float b) {
    __half2 h = __floats2half2_rn(a, b);
    return *(unsigned*)&h;
}

__global__ __launch_bounds__(320) void splat_kernel(
    const float* __restrict__ im,
    const float* __restrict__ disp,
    float* __restrict__ out)
{
    __shared__ __half2 sA[2][WW];   // (c0, c1), hashed slots, per sub-row
    __shared__ __half2 sB[2][WW];   // (c2, w ), hashed slots, per sub-row

    const int row0 = blockIdx.x * 2;     // 720 even -> both rows same batch
    const int b    = row0 / HH;
    const int y0   = row0 - b * HH;
    const int tid  = threadIdx.x;
    const int xb   = tid * 4;

    // ---- zero all planes: 4 * 320 uint4 ----
    {
        uint4 z = make_uint4(0u, 0u, 0u, 0u);
        ((uint4*)sA[0])[tid] = z;
        ((uint4*)sA[1])[tid] = z;
        ((uint4*)sB[0])[tid] = z;
        ((uint4*)sB[1])[tid] = z;
    }
    __syncthreads();

    const float* im_b = im  + (size_t)b * CHAN * HW;
    float*       o_b  = out + (size_t)b * CHAN * HW;

    #pragma unroll
    for (int r = 0; r < 2; r++) {
        const int y = y0 + r;
        const float4* d_row4 = (const float4*)(disp + (size_t)(row0 + r) * WW);
        const float*  im_row = im_b + (size_t)y * WW;

        const unsigned baseA = (unsigned)__cvta_generic_to_shared(sA[r]);
        const unsigned baseB = (unsigned)__cvta_generic_to_shared(sB[r]);

        float4 d4 = d_row4[tid];
        float4 c0 = ((const float4*)(im_row))[tid];
        float4 c1 = ((const float4*)(im_row + HW))[tid];
        float4 c2 = ((const float4*)(im_row + 2 * HW))[tid];

        const float dd[4] = {d4.x, d4.y, d4.z, d4.w};
        const float p0[4] = {c0.x, c0.y, c0.z, c0.w};
        const float p1[4] = {c1.x, c1.y, c1.z, c1.w};
        const float p2[4] = {c2.x, c2.y, c2.z, c2.w};

        // precompute payloads/addresses, then fire REDs (no return deps)
        unsigned adrA[8], adrB[8], valA[8], valB[8];
        bool ok[8];

        #pragma unroll
        for (int k = 0; k < 4; k++) {
            float d = dd[k];
            float w;
            asm("ex2.approx.f32 %0, %1;" : "=f"(w) : "f"(d * K_LOG2));
            float tx  = (float)(xb + k) - d;
            int   x0  = __float2int_rd(tx);
            float fc  = tx - (float)x0;   // weight toward x0+1
            float wc  = w * fc;           // combined weight at x0+1
            float wa  = w - wc;           // combined weight at x0

            float v0 = p0[k], v1 = p1[k], v2 = p2[k];

            int h0 = bhash(x0);
            int h1 = bhash(x0 + 1);
            ok[2 * k]     = (unsigned)x0 < WW;        // x0 in [x-21, x]
            ok[2 * k + 1] = (unsigned)(x0 + 1) < WW;
            adrA[2 * k]     = baseA + 4u * h0;
            adrB[2 * k]     = baseB + 4u * h0;
            adrA[2 * k + 1] = baseA + 4u * h1;
            adrB[2 * k + 1] = baseB + 4u * h1;
            valA[2 * k]     = pack_h2(v0 * wa, v1 * wa);
            valB[2 * k]     = pack_h2(v2 * wa, wa);
            valA[2 * k + 1] = pack_h2(v0 * wc, v1 * wc);
            valB[2 * k + 1] = pack_h2(v2 * wc, wc);
        }

        #pragma unroll
        for (int i = 0; i < 8; i++) {
            if (ok[i]) {
                red_sh_h2(adrA[i], valA[i]);
                red_sh_h2(adrB[i], valB[i]);
            }
        }
    }
    __syncthreads();

    // ---- normalize phase, both rows ----
    // bins xb..xb+3 share one hash xor which only flips bits 2..4 -> the 4
    // slots are contiguous and ordered: one uint4 per plane.
    const int g = (xb ^ ((xb >> 5) & 28)) >> 2;

    #pragma unroll
    for (int r = 0; r < 2; r++) {
        float* o_row = o_b + (size_t)(y0 + r) * WW;

        uint4 ua = ((const uint4*)sA[r])[g];   // 4 pixels of (c0,c1)
        uint4 ub = ((const uint4*)sB[r])[g];   // 4 pixels of (c2,w)
        const unsigned va[4] = {ua.x, ua.y, ua.z, ua.w};
        const unsigned vb[4] = {ub.x, ub.y, ub.z, ub.w};

        float4 r0, r1, r2;
        float* r0p = &r0.x; float* r1p = &r1.x; float* r2p = &r2.x;
        #pragma unroll
        for (int j = 0; j < 4; j++) {
            __half2 a  = *(const __half2*)&va[j];
            __half2 bb = *(const __half2*)&vb[j];
            float n0 = __low2float(a),  n1 = __high2float(a);
            float n2 = __low2float(bb), ws = __high2float(bb);
            float inv;
            asm("rcp.approx.f32 %0, %1;" : "=f"(inv) : "f"(fmaxf(ws, EPSV)));
            r0p[j] = n0 * inv;
            r1p[j] = n1 * inv;
            r2p[j] = n2 * inv;
        }
        ((float4*)o_row)[tid]            = r0;
        ((float4*)(o_row + HW))[tid]     = r1;
        ((float4*)(o_row + 2 * HW))[tid] = r2;
    }
}

extern "C" void kernel_launch(void* const* d_in, const int* in_sizes, int n_in,
                              void* d_out, int out_size) {
    const float* im   = (const float*)d_in[0];   // [8,3,720,1280] fp32
    const float* disp = (const float*)d_in[1];   // [8,1,720,1280] fp32
    float* out = (float*)d_out;                  // [8,3,720,1280] fp32

    splat_kernel<<<NROWS / 2, 320>>>(im, disp, out);
}

// round 12
// speedup vs baseline: 1.0317x; 1.0317x over previous
#include <cuda_runtime.h>
#include <cuda_fp16.h>

// Problem shape (fixed by the dataset)
#define BATCH 8
#define CHAN  3
#define HH    720
#define WW    1280
#define HW    (HH * WW)
#define NROWS (BATCH * HH)
#define NT    256
#define EPSV  1e-6f
#define K_LOG2 0.49978218f     // log2(1.414)

// flow_y == 0 -> 1-D row splat: pixel x hits bins x0=floor(x-d) and x0+1.
// (c0,c1) and (c2,wsum) accumulate as two __half2 shared planes via
// return-free red.shared.add.noftz.f16x2 (4 REDs/pixel = exact payload
// floor: 8 f16 scalars / 2 per 32-bit RED; RED lane rate ~3 lanes/cyc/SM
// pins l1tex busy at ~46us, mapping-invariant).
//
// R12: 256 threads/block (5 px/thread: 4 blocked + 1 tail) instead of 320.
// 320-thread blocks waste the 2048-thread SM ceiling (6x320=1920) and
// quantize into 7 waves; 8x256=2048 hits 100% with 5 fuller waves ->
// converts RED-pipe idle into overlap.
__device__ __forceinline__ int bhash(int bin) {
    return bin ^ ((bin >> 5) & 28);
}

__device__ __forceinline__ void red_sh_h2(unsigned addr, unsigned val) {
    asm volatile("red.shared.add.noftz.f16x2 [%0], %1;"
                 :: "r"(addr), "r"(val) : "memory");
}

__device__ __forceinline__ unsigned pack_h2(float a, float b) {
    __half2 h = __floats2half2_rn(a, b);
    return *(unsigned*)&h;
}

// splat one pixel: compute payloads and fire up to 4 REDs
__device__ __forceinline__ void splat_px(
    int x, float d, float v0, float v1, float v2,
    unsigned baseA, unsigned baseB)
{
    float w;
    asm("ex2.approx.f32 %0, %1;" : "=f"(w) : "f"(d * K_LOG2));
    float tx  = (float)x - d;
    int   x0  = __float2int_rd(tx);
    float fc  = tx - (float)x0;   // weight toward x0+1
    float wc  = w * fc;           // combined weight at x0+1
    float wa  = w - wc;           // combined weight at x0

    if ((unsigned)x0 < WW) {      // x0 in [x-21, x]
        unsigned h0 = 4u * bhash(x0);
        red_sh_h2(baseA + h0, pack_h2(v0 * wa, v1 * wa));
        red_sh_h2(baseB + h0, pack_h2(v2 * wa, wa));
    }
    int x1 = x0 + 1;
    if ((unsigned)x1 < WW) {
        unsigned h1 = 4u * bhash(x1);
        red_sh_h2(baseA + h1, pack_h2(v0 * wc, v1 * wc));
        red_sh_h2(baseB + h1, pack_h2(v2 * wc, wc));
    }
}

__global__ __launch_bounds__(NT) void splat_kernel(
    const float* __restrict__ im,
    const float* __restrict__ disp,
    float* __restrict__ out)
{
    __shared__ __half2 sA[WW];   // (c0, c1), hashed slots
    __shared__ __half2 sB[WW];   // (c2, w ), hashed slots

    const int row = blockIdx.x;      // b*HH + y
    const int b   = row / HH;
    const int y   = row - b * HH;
    const int tid = threadIdx.x;

    const unsigned baseA = (unsigned)__cvta_generic_to_shared(sA);
    const unsigned baseB = (unsigned)__cvta_generic_to_shared(sB);

    // ---- zero both planes: 2 * 320 uint4, 256 threads ----
    {
        uint4 z = make_uint4(0u, 0u, 0u, 0u);
        ((uint4*)sA)[tid] = z;
        ((uint4*)sB)[tid] = z;
        if (tid < 64) {
            ((uint4*)sA)[NT + tid] = z;
            ((uint4*)sB)[NT + tid] = z;
        }
    }
    __syncthreads();

    const float* d_row  = disp + (size_t)row * WW;
    const float* im_row = im  + (size_t)b * CHAN * HW + (size_t)y * WW;
    float*       o_row  = out + (size_t)b * CHAN * HW + (size_t)y * WW;

    // ---- splat: pixels 4t..4t+3 (vectorized) + tail pixel 1024+t ----
    const int xb = tid * 4;
    float4 d4 = ((const float4*)d_row)[tid];
    float4 c0 = ((const float4*)(im_row))[tid];
    float4 c1 = ((const float4*)(im_row + HW))[tid];
    float4 c2 = ((const float4*)(im_row + 2 * HW))[tid];

    const int xt = 4 * NT + tid;              // 1024 + tid
    float dt  = d_row[xt];
    float t0  = im_row[xt];
    float t1  = im_row[HW + xt];
    float t2  = im_row[2 * HW + xt];

    splat_px(xb,     d4.x, c0.x, c1.x, c2.x, baseA, baseB);
    splat_px(xb + 1, d4.y, c0.y, c1.y, c2.y, baseA, baseB);
    splat_px(xb + 2, d4.z, c0.z, c1.z, c2.z, baseA, baseB);
    splat_px(xb + 3, d4.w, c0.w, c1.w, c2.w, baseA, baseB);
    splat_px(xt,     dt,   t0,   t1,   t2,   baseA, baseB);
    __syncthreads();

    // ---- normalize: bins 4t..4t+3 via uint4 (hash keeps aligned groups
    // contiguous/ordered) + tail bin 1024+t scalar ----
    const int g = (xb ^ ((xb >> 5) & 28)) >> 2;
    uint4 ua = ((const uint4*)sA)[g];
    uint4 ub = ((const uint4*)sB)[g];
    const unsigned va[4] = {ua.x, ua.y, ua.z, ua.w};
    const unsigned vb[4] = {ub.x, ub.y, ub.z, ub.w};

    float4 r0, r1, r2;
    float* r0p = &r0.x; float* r1p = &r1.x; float* r2p = &r2.x;
    #pragma unroll
    for (int j = 0; j < 4; j++) {
        __half2 a  = *(const __half2*)&va[j];
        __half2 bb = *(const __half2*)&vb[j];
        float n0 = __low2float(a),  n1 = __high2float(a);
        float n2 = __low2float(bb), ws = __high2float(bb);
        float inv;
        asm("rcp.approx.f32 %0, %1;" : "=f"(inv) : "f"(fmaxf(ws, EPSV)));
        r0p[j] = n0 * inv;
        r1p[j] = n1 * inv;
        r2p[j] = n2 * inv;
    }
    ((float4*)o_row)[tid]            = r0;
    ((float4*)(o_row + HW))[tid]     = r1;
    ((float4*)(o_row + 2 * HW))[tid] = r2;

    {
        int st = bhash(xt);
        __half2 a  = sA[st];
        __half2 bb = sB[st];
        float n0 = __low2float(a),  n1 = __high2float(a);
        float n2 = __low2float(bb), ws = __high2float(bb);
        float inv;
        asm("rcp.approx.f32 %0, %1;" : "=f"(inv) : "f"(fmaxf(ws, EPSV)));
        o_row[xt]          = n0 * inv;
        o_row[HW + xt]     = n1 * inv;
        o_row[2 * HW + xt] = n2 * inv;
    }
}

extern "C" void kernel_launch(void* const* d_in, const int* in_sizes, int n_in,
                              void* d_out, int out_size) {
    const float* im   = (const float*)d_in[0];   // [8,3,720,1280] fp32
    const float* disp = (const float*)d_in[1];   // [8,1,720,1280] fp32
    float* out = (float*)d_out;                  // [8,3,720,1280] fp32

    splat_kernel<<<NROWS, NT>>>(im, disp, out);
}